// round 13
// baseline (speedup 1.0000x reference)
#include <cuda_runtime.h>
#include <cuda_bf16.h>

// MultiLoss: actor_loss = (1/B) * sum_{b,t} log(policies[b,t,actions[b,t]]) * (ea[b]-adv[b])
// B=4096, T=200, A=64. actions int32.
// Engine: EPT=4 / 800 CTAs / 256 thr + L2 evict_last retention (proven ~12.8us total).
// Reduction: fence-FREE single-kernel last-block scheme using release/acquire
// (no CCTL.IVALL L1 flush, unlike __threadfence) + __ldcg partial reads.

#define B_DIM 4096
#define T_DIM 200
#define A_DIM 64
#define TOTAL (B_DIM * T_DIM)          // 819200
#define THREADS 256
#define EPT 4                           // elements per thread (int4 action load)
#define GRID (TOTAL / (THREADS * EPT))  // 800, exact

__device__ float g_partials[GRID];
__device__ unsigned int g_ticket = 0;

__device__ __forceinline__ unsigned long long make_evict_last_policy() {
    unsigned long long pol;
    asm volatile("createpolicy.fractional.L2::evict_last.b64 %0, 1.0;" : "=l"(pol));
    return pol;
}

__device__ __forceinline__ float ldg_el(const float* p, unsigned long long pol) {
    float v;
    asm volatile("ld.global.nc.L2::cache_hint.f32 %0, [%1], %2;"
                 : "=f"(v) : "l"(p), "l"(pol));
    return v;
}

__device__ __forceinline__ int4 ldg_el_i4(const int4* p, unsigned long long pol) {
    int4 v;
    asm volatile("ld.global.nc.L2::cache_hint.v4.s32 {%0,%1,%2,%3}, [%4], %5;"
                 : "=r"(v.x), "=r"(v.y), "=r"(v.z), "=r"(v.w) : "l"(p), "l"(pol));
    return v;
}

__device__ __forceinline__ void st_release_gpu(float* p, float v) {
    asm volatile("st.global.release.gpu.f32 [%0], %1;" :: "l"(p), "f"(v) : "memory");
}

__device__ __forceinline__ unsigned int atom_add_acqrel_gpu(unsigned int* p, unsigned int v) {
    unsigned int old;
    asm volatile("atom.global.add.acq_rel.gpu.u32 %0, [%1], %2;"
                 : "=r"(old) : "l"(p), "r"(v) : "memory");
    return old;
}

__global__ __launch_bounds__(THREADS) void multiloss_kernel(
    const float* __restrict__ policies,   // [B, T, A] f32
    const int*   __restrict__ actions,    // [B, T] i32
    const float* __restrict__ ea,         // [B]
    const float* __restrict__ adv,        // [B]
    float* __restrict__ out)
{
    const int tid  = blockIdx.x * THREADS + threadIdx.x;
    const int base = tid * EPT;           // first flat element index (b*T + t)

    const unsigned long long pol = make_evict_last_policy();

    // 1 coalesced 16B load -> 4 action indices (retained in L2)
    const int4 act = ldg_el_i4(reinterpret_cast<const int4*>(actions) + tid, pol);

    // 4 independent scattered gathers, biased to stay L2-resident
    const float p0 = ldg_el(&policies[(size_t)(base + 0) * A_DIM + act.x], pol);
    const float p1 = ldg_el(&policies[(size_t)(base + 1) * A_DIM + act.y], pol);
    const float p2 = ldg_el(&policies[(size_t)(base + 2) * A_DIM + act.z], pol);
    const float p3 = ldg_el(&policies[(size_t)(base + 3) * A_DIM + act.w], pol);

    // per-element batch row & weight (warp-broadcast cache hits)
    const int b0 = (base + 0) / T_DIM;
    const int b1 = (base + 1) / T_DIM;
    const int b2 = (base + 2) / T_DIM;
    const int b3 = (base + 3) / T_DIM;

    const float w0 = __ldg(&ea[b0]) - __ldg(&adv[b0]);
    const float w1 = __ldg(&ea[b1]) - __ldg(&adv[b1]);
    const float w2 = __ldg(&ea[b2]) - __ldg(&adv[b2]);
    const float w3 = __ldg(&ea[b3]) - __ldg(&adv[b3]);

    float acc;
    acc = __logf(p0) * w0;
    acc = fmaf(__logf(p1), w1, acc);
    acc = fmaf(__logf(p2), w2, acc);
    acc = fmaf(__logf(p3), w3, acc);

    // warp reduce
    #pragma unroll
    for (int o = 16; o > 0; o >>= 1)
        acc += __shfl_down_sync(0xffffffff, acc, o);

    __shared__ float ws[THREADS / 32];
    __shared__ bool is_last;
    const int wid = threadIdx.x >> 5;
    const int lid = threadIdx.x & 31;
    if (lid == 0) ws[wid] = acc;
    __syncthreads();

    if (threadIdx.x == 0) {
        float s = 0.0f;
        #pragma unroll
        for (int i = 0; i < THREADS / 32; i++) s += ws[i];
        // release store orders the partial before the ticket increment,
        // WITHOUT a gpu-scope fence (no L1D flush).
        st_release_gpu(&g_partials[blockIdx.x], s);
        const unsigned int t = atom_add_acqrel_gpu(&g_ticket, 1u);
        is_last = (t == GRID - 1);
    }
    __syncthreads();

    // Last CTA: its acq_rel ticket read synchronizes-with all 799 releases.
    // Read partials via L2 (__ldcg) — this CTA never cached them in L1.
    if (is_last) {
        float s = 0.0f;
        #pragma unroll 4
        for (int i = threadIdx.x; i < GRID; i += THREADS)
            s += __ldcg(&g_partials[i]);
        #pragma unroll
        for (int o = 16; o > 0; o >>= 1)
            s += __shfl_down_sync(0xffffffff, s, o);
        if (lid == 0) ws[wid] = s;
        __syncthreads();
        if (threadIdx.x == 0) {
            float r = 0.0f;
            #pragma unroll
            for (int i = 0; i < THREADS / 32; i++) r += ws[i];
            out[0] = r * (1.0f / (float)B_DIM);
            g_ticket = 0;  // reset for next graph replay (kernel boundary orders it)
        }
    }
}

extern "C" void kernel_launch(void* const* d_in, const int* in_sizes, int n_in,
                              void* d_out, int out_size) {
    const float* policies = (const float*)d_in[0];
    const int*   actions  = (const int*)d_in[1];
    const float* ea       = (const float*)d_in[2];
    const float* adv      = (const float*)d_in[3];
    float* out = (float*)d_out;

    multiloss_kernel<<<GRID, THREADS>>>(policies, actions, ea, adv, out);
}

// round 14
// speedup vs baseline: 1.0173x; 1.0173x over previous
#include <cuda_runtime.h>
#include <cuda_bf16.h>

// MultiLoss: actor_loss = (1/B) * sum_{b,t} log(policies[b,t,actions[b,t]]) * (ea[b]-adv[b])
// B=4096, T=200, A=64. actions int32.
// Engine: EPT=2 / 1600 CTAs / 256 thr (full 64-warp/SM residency in wave 1)
//         + L2 evict_last retention across graph replays.
// Reduction: plain per-CTA partial stores (overwritten each replay; no fences,
// no atomics) + tiny follow-up reduce kernel (proven fastest topology, R11).

#define B_DIM 4096
#define T_DIM 200
#define A_DIM 64
#define TOTAL (B_DIM * T_DIM)          // 819200
#define THREADS 256
#define EPT 2                           // elements per thread (int2 action load)
#define GRID (TOTAL / (THREADS * EPT))  // 1600, exact

__device__ float g_partials[GRID];

__device__ __forceinline__ unsigned long long make_evict_last_policy() {
    unsigned long long pol;
    asm volatile("createpolicy.fractional.L2::evict_last.b64 %0, 1.0;" : "=l"(pol));
    return pol;
}

__device__ __forceinline__ float ldg_el(const float* p, unsigned long long pol) {
    float v;
    asm volatile("ld.global.nc.L2::cache_hint.f32 %0, [%1], %2;"
                 : "=f"(v) : "l"(p), "l"(pol));
    return v;
}

__device__ __forceinline__ int2 ldg_el_i2(const int2* p, unsigned long long pol) {
    int2 v;
    asm volatile("ld.global.nc.L2::cache_hint.v2.s32 {%0,%1}, [%2], %3;"
                 : "=r"(v.x), "=r"(v.y) : "l"(p), "l"(pol));
    return v;
}

__global__ __launch_bounds__(THREADS) void multiloss_kernel(
    const float* __restrict__ policies,   // [B, T, A] f32
    const int*   __restrict__ actions,    // [B, T] i32
    const float* __restrict__ ea,         // [B]
    const float* __restrict__ adv)        // [B]
{
    const int tid  = blockIdx.x * THREADS + threadIdx.x;
    const int base = tid * EPT;           // first flat element index (b*T + t)

    const unsigned long long pol = make_evict_last_policy();

    // 1 coalesced 8B load -> 2 action indices (retained in L2)
    const int2 act = ldg_el_i2(reinterpret_cast<const int2*>(actions) + tid, pol);

    // 2 independent scattered gathers, biased to stay L2-resident
    const float p0 = ldg_el(&policies[(size_t)(base + 0) * A_DIM + act.x], pol);
    const float p1 = ldg_el(&policies[(size_t)(base + 1) * A_DIM + act.y], pol);

    // per-element batch row & weight (warp-broadcast cache hits)
    const int b0 = (base + 0) / T_DIM;
    const int b1 = (base + 1) / T_DIM;

    const float w0 = __ldg(&ea[b0]) - __ldg(&adv[b0]);
    const float w1 = __ldg(&ea[b1]) - __ldg(&adv[b1]);

    float acc;
    acc = __logf(p0) * w0;
    acc = fmaf(__logf(p1), w1, acc);

    // warp reduce
    #pragma unroll
    for (int o = 16; o > 0; o >>= 1)
        acc += __shfl_down_sync(0xffffffff, acc, o);

    __shared__ float ws[THREADS / 32];
    const int wid = threadIdx.x >> 5;
    const int lid = threadIdx.x & 31;
    if (lid == 0) ws[wid] = acc;
    __syncthreads();

    if (threadIdx.x == 0) {
        float s = 0.0f;
        #pragma unroll
        for (int i = 0; i < THREADS / 32; i++) s += ws[i];
        g_partials[blockIdx.x] = s;   // plain store; overwritten every replay
    }
}

// 1600 floats -> scalar. One CTA, 256 threads: vectorized float4 loads (L2 hits).
__global__ __launch_bounds__(THREADS) void reduce_kernel(float* __restrict__ out) {
    const float4* p4 = reinterpret_cast<const float4*>(g_partials);  // 400 float4s
    float s = 0.0f;
    #pragma unroll
    for (int i = threadIdx.x; i < GRID / 4; i += THREADS) {          // 400 of them
        const float4 v = p4[i];
        s += (v.x + v.y) + (v.z + v.w);
    }
    #pragma unroll
    for (int o = 16; o > 0; o >>= 1)
        s += __shfl_down_sync(0xffffffff, s, o);

    __shared__ float ws[THREADS / 32];
    const int wid = threadIdx.x >> 5;
    const int lid = threadIdx.x & 31;
    if (lid == 0) ws[wid] = s;
    __syncthreads();

    if (threadIdx.x == 0) {
        float r = 0.0f;
        #pragma unroll
        for (int i = 0; i < THREADS / 32; i++) r += ws[i];
        out[0] = r * (1.0f / (float)B_DIM);
    }
}

extern "C" void kernel_launch(void* const* d_in, const int* in_sizes, int n_in,
                              void* d_out, int out_size) {
    const float* policies = (const float*)d_in[0];
    const int*   actions  = (const int*)d_in[1];
    const float* ea       = (const float*)d_in[2];
    const float* adv      = (const float*)d_in[3];
    float* out = (float*)d_out;

    multiloss_kernel<<<GRID, THREADS>>>(policies, actions, ea, adv);
    reduce_kernel<<<1, THREADS>>>(out);
}